// round 17
// baseline (speedup 1.0000x reference)
#include <cuda_runtime.h>
#include <cuda_bf16.h>
#include <math.h>

// Problem constants
#define T_STEPS 128
#define BATCH   64
#define NTOKEN  10000
#define NB      6
#define BS      100
#define NHID    600
#define EMHA    64
#define DEC_ELEMS 81920000L
#define HX_ELEMS  38400

#define N_RNN_CTAS 32
#define N_NTILES   79
#define N_MTILES   64
#define N_DEC_TOTAL (N_MTILES * N_NTILES)   // 5056
#define N_PREP_CTAS 8

// -------------------- device scratch (no allocations allowed) --------------------
__device__ float g_outputs[T_STEPS * BATCH * NHID];
__device__ float g_gruT_ih[NB * BS * 3 * BS];         // [k][d][g]
__device__ float g_gruT_hh[NB * BS * 3 * BS];
__device__ float g_mhafcT[EMHA * BS];                 // [e][i]
__device__ float g_gateT[EMHA * BS];
__device__ int   g_flag[T_STEPS];                     // per-step rnn completion (0..32)
__device__ int   g_prep_done;                         // 0..8
__device__ int   g_dec_done;                          // 0..5056

// -------------------- helpers --------------------
__device__ __forceinline__ float sigmoidf_(float x) { return 1.f / (1.f + expf(-x)); }
__device__ __forceinline__ void ffma2(unsigned long long& a, unsigned long long x, unsigned long long y) {
    asm("fma.rn.f32x2 %0, %1, %2, %0;" : "+l"(a) : "l"(x), "l"(y));
}
__device__ __forceinline__ unsigned long long bc2(float x) {
    unsigned long long r;
    asm("mov.b64 %0, {%1, %1};" : "=l"(r) : "r"(__float_as_uint(x)));
    return r;
}
__device__ __forceinline__ float2 up2(unsigned long long a) {
    unsigned lo, hi;
    asm("mov.b64 {%0, %1}, %2;" : "=r"(lo), "=r"(hi) : "l"(a));
    return make_float2(__uint_as_float(lo), __uint_as_float(hi));
}

#define BAR_C() asm volatile("bar.sync 2, 640;" ::: "memory")
#define BAR_L() asm volatile("bar.sync 3, 384;" ::: "memory")

// -------------------- rnn smem layout (floats) --------------------
#define OFF_HX    0        // [2][600]
#define OFF_X     1200     // [2 par][2 b][600]
#define OFF_IU    3600     // [2][600]
#define OFF_HN    4800     // [2][600]
#define OFF_GX    6000     // [2][1800]
#define OFF_GH    9600     // [2][1800]
#define OFF_REDQ  13200    // [18][2][128] qp partials
#define OFF_KVL   17808    // [12][2][128] k/v partials (L private)
#define OFF_K0P   20880    // [2 par][2 b][128]
#define OFF_V0L   21392    // [2 b][128] (L private)
#define OFF_PP    21648    // [2 par][2 b][104]
#define OFF_A0    22064    // [2][8]
#define OFF_MASK  22080    // [2][8]
#define OFF_QKV   22096    // [2][1152]
#define OFF_AW    24400    // [2][144]
#define OFF_AO    24688    // [2][384]
#define OFF_FCT   25456    // 6400
#define OFF_GT    31856    // 6400
#define OFF_TOK   38256    // 256 ints
#define SMEM_FLOATS 44704
#define SMEM_BYTES  (SMEM_FLOATS * 4)   // 178816 B -> 1 CTA/SM guaranteed

// ============================================================================
// Single fused kernel.
//   blocks [0,32):  rnn, 2 batch elems each. Warp-specialized: warps 0-19 (C)
//                   run the hx-dependent chain; warps 20-31 (L) compute gh,
//                   next-step k0/v0/p, and x prefetch. 2 full barriers/step.
//   blocks [32,..): decoder tiles gated by per-step flags; first 8 dec CTAs
//                   do the one-time weight transposes; last dec CTA resets.
// Every CTA requests 174+KB smem => 1 CTA/SM; rnn CTAs are wave-1 resident.
// ============================================================================
__global__ __launch_bounds__(1024, 1)
void fused_kernel(const int* __restrict__ input, const float* __restrict__ hidden,
                  const float* __restrict__ enc,
                  const float* __restrict__ wq,     // (6,100,128)
                  const float* __restrict__ wk,     // (2,600,128) slab 0
                  const float* __restrict__ wv,     // (2,600,128) slab 0
                  const float* __restrict__ fc_w,   // (100,128)
                  const float* __restrict__ fc_b,   // (100,)
                  const float* __restrict__ mwq,    // (6,100,64)
                  const float* __restrict__ mwk,
                  const float* __restrict__ mwv,
                  const float* __restrict__ mfc_b,
                  const float* __restrict__ mg_b,
                  const float* __restrict__ b_ih,   // (6,300)
                  const float* __restrict__ b_hh,   // (6,300)
                  const float* __restrict__ gru_w_ih, // raw (6,300,100)
                  const float* __restrict__ gru_w_hh,
                  const float* __restrict__ mfc_raw,  // (100,64)
                  const float* __restrict__ mgate_raw,
                  const float* __restrict__ Bw,     // dec_w (10000,600)
                  const float* __restrict__ bias,   // dec_b
                  float* __restrict__ C,            // out
                  int out_size)
{
    extern __shared__ float smem[];
    const int tid = threadIdx.x;

    if (blockIdx.x >= N_RNN_CTAS) {
        // ================= decoder path =================
        const int d  = blockIdx.x - N_RNN_CTAS;

        if (d < N_PREP_CTAS) {
            const int CH = (NB * 3 * BS * BS) / N_PREP_CTAS;   // 22500
            for (int i = d * CH + tid; i < (d + 1) * CH; i += 1024) {
                int k = i / (3 * BS * BS);
                int r = i % (3 * BS * BS);
                int g = r / BS;
                int dd = r % BS;
                int dst = k * (BS * 3 * BS) + dd * (3 * BS) + g;
                g_gruT_ih[dst] = gru_w_ih[i];
                g_gruT_hh[dst] = gru_w_hh[i];
            }
            if (d == 0) {
                for (int i = tid; i < BS * EMHA; i += 1024) {
                    int r = i / EMHA, e = i % EMHA;
                    g_mhafcT[e * BS + r] = mfc_raw[i];
                    g_gateT[e * BS + r]  = mgate_raw[i];
                }
            }
            __syncthreads();
            if (tid == 0) { __threadfence(); atomicAdd(&g_prep_done, 1); }
        }

        if (tid >= 512) return;

        const int mt = d / N_NTILES, nt = d % N_NTILES;
        const int bm = mt * 128, bn = nt * 128;

        if (tid == 0) {
            while (atomicAdd(&g_flag[2 * mt], 0)     < N_RNN_CTAS) __nanosleep(256);
            while (atomicAdd(&g_flag[2 * mt + 1], 0) < N_RNN_CTAS) __nanosleep(256);
            __threadfence();
        }
        asm volatile("bar.sync 1, 512;" ::: "memory");

        float* As = smem;          // [2][8][128]
        float* Bs = smem + 2048;

        const int arow = tid >> 2;
        const int kp   = (tid & 3) * 2;
        const float* Ap = g_outputs + (long)(bm + arow) * NHID + kp;
        int brow = bn + arow; if (brow > NTOKEN - 1) brow = NTOKEN - 1;
        const float* Bp = Bw + (long)brow * NHID + kp;

        const int tx = tid & 15, ty = tid >> 4;

        unsigned long long acc[4][4];
        #pragma unroll
        for (int i = 0; i < 4; i++)
            #pragma unroll
            for (int j = 0; j < 4; j++) acc[i][j] = 0ull;

        float2 ra = *(const float2*)Ap;
        float2 rb = *(const float2*)Bp;
        int buf = 0;
        As[(0 * 8 + kp) * 128 + arow]     = ra.x;
        As[(0 * 8 + kp + 1) * 128 + arow] = ra.y;
        Bs[(0 * 8 + kp) * 128 + arow]     = rb.x;
        Bs[(0 * 8 + kp + 1) * 128 + arow] = rb.y;
        asm volatile("bar.sync 1, 512;" ::: "memory");

        const int NKT = NHID / 8;
        for (int kt = 0; kt < NKT; kt++) {
            if (kt < NKT - 1) {
                ra = *(const float2*)(Ap + (kt + 1) * 8);
                rb = *(const float2*)(Bp + (kt + 1) * 8);
            }
            #pragma unroll
            for (int kk = 0; kk < 8; kk++) {
                float4 a = *(const float4*)(As + (buf * 8 + kk) * 128 + ty * 4);
                ulonglong2 b0 = *(const ulonglong2*)(Bs + (buf * 8 + kk) * 128 + tx * 8);
                ulonglong2 b1 = *(const ulonglong2*)(Bs + (buf * 8 + kk) * 128 + tx * 8 + 4);
                float av[4] = {a.x, a.y, a.z, a.w};
                unsigned long long bbv[4] = {b0.x, b0.y, b1.x, b1.y};
                #pragma unroll
                for (int i = 0; i < 4; i++) {
                    unsigned long long aa = bc2(av[i]);
                    #pragma unroll
                    for (int j = 0; j < 4; j++) ffma2(acc[i][j], aa, bbv[j]);
                }
            }
            if (kt < NKT - 1) {
                int nb = buf ^ 1;
                As[(nb * 8 + kp) * 128 + arow]     = ra.x;
                As[(nb * 8 + kp + 1) * 128 + arow] = ra.y;
                Bs[(nb * 8 + kp) * 128 + arow]     = rb.x;
                Bs[(nb * 8 + kp + 1) * 128 + arow] = rb.y;
                asm volatile("bar.sync 1, 512;" ::: "memory");
                buf = nb;
            }
        }

        const int n0 = bn + tx * 8;
        #pragma unroll
        for (int i = 0; i < 4; i++) {
            int m = bm + ty * 4 + i;
            float v[8];
            #pragma unroll
            for (int j = 0; j < 4; j++) {
                float2 p = up2(acc[i][j]);
                v[2 * j] = p.x; v[2 * j + 1] = p.y;
            }
            long base = (long)m * NTOKEN + n0;
            if (n0 + 8 <= NTOKEN) {
                #pragma unroll
                for (int j = 0; j < 8; j++) v[j] += bias[n0 + j];
                *(float4*)(C + base)     = make_float4(v[0], v[1], v[2], v[3]);
                *(float4*)(C + base + 4) = make_float4(v[4], v[5], v[6], v[7]);
            } else {
                for (int j = 0; j < 8; j++)
                    if (n0 + j < NTOKEN) C[base + j] = v[j] + bias[n0 + j];
            }
        }

        asm volatile("bar.sync 1, 512;" ::: "memory");
        if (tid == 0) {
            __threadfence();
            int old = atomicAdd(&g_dec_done, 1);
            if (old == N_DEC_TOTAL - 1) {
                for (int i = 0; i < T_STEPS; i++) g_flag[i] = 0;
                g_prep_done = 0;
                g_dec_done  = 0;
                __threadfence();
            }
        }
        return;
    }

    // ================= rnn path =================
    const int b0 = blockIdx.x * 2;

    float* s_hx   = smem + OFF_HX;
    float* s_xb   = smem + OFF_X;
    float* s_iu   = smem + OFF_IU;
    float* s_hn   = smem + OFF_HN;
    float* s_gx   = smem + OFF_GX;
    float* s_gh   = smem + OFF_GH;
    float* s_redq = smem + OFF_REDQ;
    float* s_kvL  = smem + OFF_KVL;
    float* s_k0p  = smem + OFF_K0P;
    float* s_v0L  = smem + OFF_V0L;
    float* s_pP   = smem + OFF_PP;
    float* s_a0   = smem + OFF_A0;
    float* s_mask = smem + OFF_MASK;
    float* s_qkv  = smem + OFF_QKV;
    float* s_aw   = smem + OFF_AW;
    float* s_ao   = smem + OFF_AO;
    float* s_fcT  = smem + OFF_FCT;
    float* s_gT   = smem + OFF_GT;
    int*   s_tok  = (int*)(smem + OFF_TOK);

    if (tid == 0) {
        while (atomicAdd(&g_prep_done, 0) < N_PREP_CTAS) __nanosleep(128);
        __threadfence();
    }
    __syncthreads();

    // bootstrap loads: hx, fc/gate smem caches, tokens
    for (int j = tid; j < 1200; j += 1024)
        s_hx[j] = hidden[(long)(b0 + j / 600) * NHID + (j % 600)];
    for (int j = tid; j < 6400; j += 1024) {
        s_fcT[j] = g_mhafcT[j];
        s_gT[j]  = g_gateT[j];
    }
    if (tid < 256) {
        int t = tid >> 1, bb = tid & 1;
        s_tok[tid] = input[t * BATCH + b0 + bb];
    }
    __syncthreads();
    // x(0) and x(1)
    if (tid < 600) {
        int pb = tid / 300, bb = (tid % 300) / 150, j = tid % 150;
        long tok = s_tok[pb * 2 + bb];
        *(float4*)(s_xb + pb * 1200 + bb * 600 + j * 4) = *(const float4*)(enc + tok * NHID + j * 4);
    }
    __syncthreads();

    // bootstrap: L group computes k0/v0(0) and p(0) into parity 0
    if (tid >= 640) {
        int ltid = tid - 640, lw = ltid >> 5, llane = ltid & 31, ll4 = llane * 4;
        {
            int kv = lw / 6, ws = lw % 6;
            const float* W = (kv ? wv : wk);
            const float* sx = s_xb;   // parity 0 = x(0)
            unsigned long long a00 = 0, a01 = 0, a10 = 0, a11 = 0;
            for (int d = ws; d < 600; d += 6) {
                ulonglong2 wt = *(const ulonglong2*)(W + d * 128 + ll4);
                unsigned long long x0 = bc2(sx[d]);
                unsigned long long x1 = bc2(sx[600 + d]);
                ffma2(a00, x0, wt.x); ffma2(a01, x0, wt.y);
                ffma2(a10, x1, wt.x); ffma2(a11, x1, wt.y);
            }
            float2 p0 = up2(a00), p1 = up2(a01);
            *(float4*)(s_kvL + (lw * 2 + 0) * 128 + ll4) = make_float4(p0.x, p0.y, p1.x, p1.y);
            p0 = up2(a10); p1 = up2(a11);
            *(float4*)(s_kvL + (lw * 2 + 1) * 128 + ll4) = make_float4(p0.x, p0.y, p1.x, p1.y);
        }
        BAR_L();
        for (int j = ltid; j < 512; j += 384) {
            int kv = j >> 8, bb = (j >> 7) & 1, e = j & 127;
            float s = 0.f;
            #pragma unroll
            for (int ws = 0; ws < 6; ws++) s += s_kvL[((kv * 6 + ws) * 2 + bb) * 128 + e];
            if (kv) s_v0L[bb * 128 + e] = s; else s_k0p[bb * 128 + e] = s;
        }
        BAR_L();
        for (int r = lw; r < 200; r += 12) {
            int bb = r / 100, i = r % 100;
            float4 f = *(const float4*)(fc_w + i * 128 + ll4);
            const float* vv = s_v0L + bb * 128 + ll4;
            float acc = f.x * vv[0] + f.y * vv[1] + f.z * vv[2] + f.w * vv[3];
            #pragma unroll
            for (int o = 16; o > 0; o >>= 1) acc += __shfl_xor_sync(0xffffffffu, acc, o);
            if (llane == 0) s_pP[bb * 104 + i] = acc;
        }
    }
    __syncthreads();

    const bool inC = tid < 640;

    for (int t = 0; t < T_STEPS; t++) {
        const int par = t & 1;

        if (inC) {
            const int w = tid >> 5, lane = tid & 31, l4 = lane * 4;
            // ---- C seg1.1: qp partials (warps 0-17, d-split 3) ----
            if (w < 18) {
                int n = w / 3, d0 = w % 3;
                const float* W  = wq + n * 100 * 128 + l4;
                const float* h0 = s_hx + n * 100;
                unsigned long long a00 = 0, a01 = 0, a10 = 0, a11 = 0;
                for (int d = d0; d < 100; d += 3) {
                    ulonglong2 wt = *(const ulonglong2*)(W + d * 128);
                    unsigned long long x0 = bc2(h0[d]);
                    unsigned long long x1 = bc2(h0[600 + d]);
                    ffma2(a00, x0, wt.x); ffma2(a01, x0, wt.y);
                    ffma2(a10, x1, wt.x); ffma2(a11, x1, wt.y);
                }
                float2 p0 = up2(a00), p1 = up2(a01);
                *(float4*)(s_redq + (w * 2 + 0) * 128 + l4) = make_float4(p0.x, p0.y, p1.x, p1.y);
                p0 = up2(a10); p1 = up2(a11);
                *(float4*)(s_redq + (w * 2 + 1) * 128 + l4) = make_float4(p0.x, p0.y, p1.x, p1.y);
            }
            BAR_C();
            // ---- C seg1.2: scores (warps 0-11) ----
            if (w < 12) {
                int bb = w / 6, n = w % 6;
                float acc = 0.f;
                #pragma unroll
                for (int es = 0; es < 4; es++) {
                    int e = lane + 32 * es;
                    float qv = s_redq[((n * 3 + 0) * 2 + bb) * 128 + e]
                             + s_redq[((n * 3 + 1) * 2 + bb) * 128 + e]
                             + s_redq[((n * 3 + 2) * 2 + bb) * 128 + e];
                    acc += qv * s_k0p[par * 256 + bb * 128 + e];
                }
                #pragma unroll
                for (int o = 16; o > 0; o >>= 1) acc += __shfl_xor_sync(0xffffffffu, acc, o);
                if (lane == 0) s_a0[bb * 8 + n] = sigmoidf_(acc * 0.08838834764831845f);
            }
            BAR_C();
            // ---- C seg1.3: topk mask + iu ----
            if (tid >= 636 && tid < 638) {
                int bb = tid - 636;
                float v[6];
                #pragma unroll
                for (int n = 0; n < 6; n++) v[n] = s_a0[bb * 8 + n];
                #pragma unroll
                for (int a = 0; a < 6; a++)
                    #pragma unroll
                    for (int c = a + 1; c < 6; c++)
                        if (v[c] > v[a]) { float tmp = v[a]; v[a] = v[c]; v[c] = tmp; }
                float thr = v[3] - 0.01f;
                #pragma unroll
                for (int n = 0; n < 6; n++) s_mask[bb * 8 + n] = (s_a0[bb * 8 + n] > thr) ? 1.f : 0.f;
            }
            for (int j = tid; j < 1200; j += 640) {
                int bb = j / 600, i = j % 600, n = i / 100, ii = i % 100;
                s_iu[bb * 600 + i] = s_a0[bb * 8 + n] * s_pP[par * 208 + bb * 104 + ii] + fc_b[ii];
            }
            BAR_C();
            // ---- C seg1.4: gx (450 threads) ----
            if (tid < 450) {
                int kl = tid / 75, g4 = (tid % 75) * 4;
                const float* WT = g_gruT_ih + kl * 30000 + g4;
                const float* s0 = s_iu + kl * 100;
                unsigned long long a00 = 0, a01 = 0, a10 = 0, a11 = 0;
                #pragma unroll 4
                for (int d = 0; d < 100; d++) {
                    ulonglong2 wt = *(const ulonglong2*)(WT + d * 300);
                    unsigned long long x0 = bc2(s0[d]);
                    unsigned long long x1 = bc2(s0[600 + d]);
                    ffma2(a00, x0, wt.x); ffma2(a01, x0, wt.y);
                    ffma2(a10, x1, wt.x); ffma2(a11, x1, wt.y);
                }
                float4 bi = *(const float4*)(b_ih + kl * 300 + g4);
                float2 p0 = up2(a00), p1 = up2(a01);
                *(float4*)(s_gx + kl * 300 + g4) =
                    make_float4(p0.x + bi.x, p0.y + bi.y, p1.x + bi.z, p1.y + bi.w);
                p0 = up2(a10); p1 = up2(a11);
                *(float4*)(s_gx + 1800 + kl * 300 + g4) =
                    make_float4(p0.x + bi.x, p0.y + bi.y, p1.x + bi.z, p1.y + bi.w);
            }
        } else {
            // ---- L seg1: gh = hx @ W_hh^T + b_hh ----
            int ltid = tid - 640;
            for (int t2 = ltid; t2 < 450; t2 += 384) {
                int kl = t2 / 75, g4 = (t2 % 75) * 4;
                const float* WT = g_gruT_hh + kl * 30000 + g4;
                const float* s0 = s_hx + kl * 100;
                unsigned long long a00 = 0, a01 = 0, a10 = 0, a11 = 0;
                #pragma unroll 4
                for (int d = 0; d < 100; d++) {
                    ulonglong2 wt = *(const ulonglong2*)(WT + d * 300);
                    unsigned long long x0 = bc2(s0[d]);
                    unsigned long long x1 = bc2(s0[600 + d]);
                    ffma2(a00, x0, wt.x); ffma2(a01, x0, wt.y);
                    ffma2(a10, x1, wt.x); ffma2(a11, x1, wt.y);
                }
                float4 bi = *(const float4*)(b_hh + kl * 300 + g4);
                float2 p0 = up2(a00), p1 = up2(a01);
                *(float4*)(s_gh + kl * 300 + g4) =
                    make_float4(p0.x + bi.x, p0.y + bi.y, p1.x + bi.z, p1.y + bi.w);
                p0 = up2(a10); p1 = up2(a11);
                *(float4*)(s_gh + 1800 + kl * 300 + g4) =
                    make_float4(p0.x + bi.x, p0.y + bi.y, p1.x + bi.z, p1.y + bi.w);
            }
        }
        __syncthreads();   // R2: gx+gh ready

        if (inC) {
            // ---- C seg2.1: GRU elementwise ----
            for (int j = tid; j < 1200; j += 640) {
                int bb = j / 600, i = j % 600, kl = i / 100, jj = i % 100;
                int base = bb * 1800 + kl * 300 + jj;
                float r  = sigmoidf_(s_gx[base]       + s_gh[base]);
                float z  = sigmoidf_(s_gx[base + 100] + s_gh[base + 100]);
                float nn = tanhf(s_gx[base + 200] + r * s_gh[base + 200]);
                s_hn[bb * 600 + i] = (1.f - z) * nn + z * s_hx[bb * 600 + i];
            }
            BAR_C();
            // ---- C seg2.2: MHA q/k/v projections (288 threads) ----
            if (tid < 288) {
                int which = tid / 96, r = tid % 96, n = r / 16, e4 = (r % 16) * 4;
                const float* W = (which == 0 ? mwq : (which == 1 ? mwk : mwv))
                                 + n * 100 * 64 + e4;
                const float* h0 = s_hn + n * 100;
                unsigned long long a00 = 0, a01 = 0, a10 = 0, a11 = 0;
                #pragma unroll 4
                for (int d = 0; d < 100; d++) {
                    ulonglong2 wt = *(const ulonglong2*)(W + d * 64);
                    unsigned long long x0 = bc2(h0[d]);
                    unsigned long long x1 = bc2(h0[600 + d]);
                    ffma2(a00, x0, wt.x); ffma2(a01, x0, wt.y);
                    ffma2(a10, x1, wt.x); ffma2(a11, x1, wt.y);
                }
                int o = which * 384 + n * 64 + e4;
                float2 p0 = up2(a00), p1 = up2(a01);
                *(float4*)(s_qkv + o) = make_float4(p0.x, p0.y, p1.x, p1.y);
                p0 = up2(a10); p1 = up2(a11);
                *(float4*)(s_qkv + 1152 + o) = make_float4(p0.x, p0.y, p1.x, p1.y);
            }
            BAR_C();
            // ---- C seg2.3: merged attention (8 warps, warp-local) ----
            if (tid < 256) {
                int w8 = tid >> 5, lane8 = tid & 31;
                int bb = w8 >> 2, h = w8 & 3;
                const float* qb = s_qkv + bb * 1152;
                const float* kb = qb + 384;
                const float* vb = qb + 768;
                float* aw = s_aw + bb * 144 + h * 36;
                for (int s = lane8; s < 36; s += 32) {
                    int i = s / 6, j = s % 6;
                    const float* q = qb + i * 64 + h * 16;
                    const float* k = kb + j * 64 + h * 16;
                    float acc = 0.f;
                    #pragma unroll
                    for (int d2 = 0; d2 < 16; d2++) acc += q[d2] * k[d2];
                    aw[i * 6 + j] = acc * 0.25f;
                }
                __syncwarp();
                if (lane8 < 6) {
                    float* row = aw + lane8 * 6;
                    float m = row[0];
                    #pragma unroll
                    for (int j = 1; j < 6; j++) m = fmaxf(m, row[j]);
                    float ex[6]; float ssum = 0.f;
                    #pragma unroll
                    for (int j = 0; j < 6; j++) { ex[j] = expf(row[j] - m); ssum += ex[j]; }
                    float inv = 1.f / ssum;
                    #pragma unroll
                    for (int j = 0; j < 6; j++) row[j] = ex[j] * inv;
                }
                __syncwarp();
                for (int o = lane8; o < 96; o += 32) {
                    int n = o / 16, el = o % 16;
                    const float* awn = aw + n * 6;
                    const float* vcol = vb + h * 16 + el;
                    float acc = 0.f;
                    #pragma unroll
                    for (int j = 0; j < 6; j++) acc += awn[j] * vcol[j * 64];
                    s_ao[bb * 384 + n * 64 + h * 16 + el] = acc;
                }
            }
            BAR_C();
            // ---- C seg2.4: fc proj + gate + blend, store output ----
            if (tid < 300) {
                int bb = tid / 150, r = tid % 150, n = r / 25, i4 = (r % 25) * 4;
                const float* ao = s_ao + bb * 384 + n * 64;
                unsigned long long pr0 = 0, pr1 = 0, gt0 = 0, gt1 = 0;
                #pragma unroll 4
                for (int e = 0; e < 64; e++) {
                    ulonglong2 f = *(const ulonglong2*)(s_fcT + e * 100 + i4);
                    ulonglong2 g = *(const ulonglong2*)(s_gT + e * 100 + i4);
                    unsigned long long a2 = bc2(ao[e]);
                    ffma2(pr0, a2, f.x); ffma2(pr1, a2, f.y);
                    ffma2(gt0, a2, g.x); ffma2(gt1, a2, g.y);
                }
                float2 pa = up2(pr0), pb = up2(pr1), ga = up2(gt0), gb = up2(gt1);
                float prv[4] = {pa.x, pa.y, pb.x, pb.y};
                float gtv[4] = {ga.x, ga.y, gb.x, gb.y};
                float m = s_mask[bb * 8 + n];
                float4 o4;
                float* ov = (float*)&o4;
                #pragma unroll
                for (int c = 0; c < 4; c++) {
                    int i = i4 + c;
                    float pr = prv[c] + mfc_b[i];
                    float gt = gtv[c] + mg_b[i];
                    float hatt = sigmoidf_(gt) * tanhf(pr);
                    int hidx = bb * 600 + n * 100 + i;
                    float nh = m * hatt + (1.f - m) * s_hx[hidx];
                    s_hx[hidx] = nh;
                    ov[c] = nh;
                }
                long obase = ((long)t * BATCH + b0 + bb) * NHID + n * 100 + i4;
                *(float4*)(g_outputs + obase) = o4;
                if (t == T_STEPS - 1 && (long)out_size >= DEC_ELEMS + HX_ELEMS)
                    *(float4*)(C + DEC_ELEMS + (long)(b0 + bb) * NHID + n * 100 + i4) = o4;
            }
            __threadfence();
            BAR_C();
            if (tid == 0) atomicAdd(&g_flag[t], 1);
        } else {
            // ---- L seg2: k0/v0/p for step t+1, prefetch x(t+2) ----
            int ltid = tid - 640, lw = ltid >> 5, llane = ltid & 31, ll4 = llane * 4;
            int ts = t + 1;
            if (ts < T_STEPS) {
                int dp = ts & 1;
                const float* sx = s_xb + dp * 1200;   // x(t+1)
                {
                    int kv = lw / 6, ws = lw % 6;
                    const float* W = (kv ? wv : wk);
                    unsigned long long a00 = 0, a01 = 0, a10 = 0, a11 = 0;
                    for (int d = ws; d < 600; d += 6) {
                        ulonglong2 wt = *(const ulonglong2*)(W + d * 128 + ll4);
                        unsigned long long x0 = bc2(sx[d]);
                        unsigned long long x1 = bc2(sx[600 + d]);
                        ffma2(a00, x0, wt.x); ffma2(a01, x0, wt.y);
                        ffma2(a10, x1, wt.x); ffma2(a11, x1, wt.y);
                    }
                    float2 p0 = up2(a00), p1 = up2(a01);
                    *(float4*)(s_kvL + (lw * 2 + 0) * 128 + ll4) = make_float4(p0.x, p0.y, p1.x, p1.y);
                    p0 = up2(a10); p1 = up2(a11);
                    *(float4*)(s_kvL + (lw * 2 + 1) * 128 + ll4) = make_float4(p0.x, p0.y, p1.x, p1.y);
                }
                BAR_L();
                for (int j = ltid; j < 512; j += 384) {
                    int kv = j >> 8, bb = (j >> 7) & 1, e = j & 127;
                    float s = 0.f;
                    #pragma unroll
                    for (int ws = 0; ws < 6; ws++) s += s_kvL[((kv * 6 + ws) * 2 + bb) * 128 + e];
                    if (kv) s_v0L[bb * 128 + e] = s; else s_k0p[dp * 256 + bb * 128 + e] = s;
                }
                BAR_L();
                for (int r = lw; r < 200; r += 12) {
                    int bb = r / 100, i = r % 100;
                    float4 f = *(const float4*)(fc_w + i * 128 + ll4);
                    const float* vv = s_v0L + bb * 128 + ll4;
                    float acc = f.x * vv[0] + f.y * vv[1] + f.z * vv[2] + f.w * vv[3];
                    #pragma unroll
                    for (int o = 16; o > 0; o >>= 1) acc += __shfl_xor_sync(0xffffffffu, acc, o);
                    if (llane == 0) s_pP[dp * 208 + bb * 104 + i] = acc;
                }
                if (t + 2 < T_STEPS) {
                    for (int u = ltid; u < 300; u += 384) {
                        int bb = u / 150, j = u % 150;
                        long tok = s_tok[(t + 2) * 2 + bb];
                        *(float4*)(s_xb + ((t + 2) & 1) * 1200 + bb * 600 + j * 4) =
                            *(const float4*)(enc + tok * NHID + j * 4);
                    }
                }
            }
        }
        __syncthreads();   // R1: step boundary
    }

    if (blockIdx.x == 0 && tid == 0 && (long)out_size >= DEC_ELEMS + HX_ELEMS + 1)
        C[DEC_ELEMS + HX_ELEMS] = 0.0f;
}

extern "C" void kernel_launch(void* const* d_in, const int* in_sizes, int n_in,
                              void* d_out, int out_size) {
    const int*   input      = (const int*)  d_in[0];
    const float* hidden     = (const float*)d_in[1];
    const float* encoder_w  = (const float*)d_in[2];
    const float* inp_wq     = (const float*)d_in[3];
    const float* inp_wk     = (const float*)d_in[4];
    const float* inp_wv     = (const float*)d_in[5];
    const float* inp_fc_w   = (const float*)d_in[6];
    const float* inp_fc_b   = (const float*)d_in[7];
    const float* mha_wq     = (const float*)d_in[8];
    const float* mha_wk     = (const float*)d_in[9];
    const float* mha_wv     = (const float*)d_in[10];
    const float* mha_fc_w   = (const float*)d_in[11];
    const float* mha_fc_b   = (const float*)d_in[12];
    const float* mha_gate_w = (const float*)d_in[13];
    const float* mha_gate_b = (const float*)d_in[14];
    const float* gru_w_ih   = (const float*)d_in[15];
    const float* gru_w_hh   = (const float*)d_in[16];
    const float* gru_b_ih   = (const float*)d_in[17];
    const float* gru_b_hh   = (const float*)d_in[18];
    const float* dec_w      = (const float*)d_in[19];
    const float* dec_b      = (const float*)d_in[20];
    float* out = (float*)d_out;

    cudaFuncSetAttribute(fused_kernel, cudaFuncAttributeMaxDynamicSharedMemorySize, SMEM_BYTES);

    const int grid = N_RNN_CTAS + N_DEC_TOTAL;   // 32 + 5056
    fused_kernel<<<grid, 1024, SMEM_BYTES>>>(input, hidden, encoder_w,
                                inp_wq, inp_wk, inp_wv, inp_fc_w, inp_fc_b,
                                mha_wq, mha_wk, mha_wv, mha_fc_b, mha_gate_b,
                                gru_b_ih, gru_b_hh,
                                gru_w_ih, gru_w_hh, mha_fc_w, mha_gate_w,
                                dec_w, dec_b, out, out_size);
}